// round 5
// baseline (speedup 1.0000x reference)
#include <cuda_runtime.h>
#include <cuda_bf16.h>
#include <math.h>
#include <cstdint>

#define S_LEN 4096
#define HID   2048
#define NH    8
#define HD    256

typedef unsigned short u16;

// ------------------------- device scratch (no allocs allowed) ---------------
__device__ float g_Q [(size_t)S_LEN * HID];
__device__ float g_K [(size_t)S_LEN * HD];
__device__ float g_V [(size_t)S_LEN * HD];
__device__ float g_S [(size_t)NH * S_LEN * S_LEN];     // fp32 scores
__device__ float g_A [(size_t)S_LEN * HID];

__device__ u16 g_Xhi [(size_t)S_LEN * HID];
__device__ u16 g_Xlo [(size_t)S_LEN * HID];
__device__ u16 g_Qhi [(size_t)S_LEN * HID];
__device__ u16 g_Qlo [(size_t)S_LEN * HID];
__device__ u16 g_Khi [(size_t)S_LEN * HD];
__device__ u16 g_Klo [(size_t)S_LEN * HD];
__device__ u16 g_VThi[(size_t)HD * S_LEN];
__device__ u16 g_VTlo[(size_t)HD * S_LEN];
__device__ u16 g_Phi [(size_t)NH * S_LEN * S_LEN];     // 256 MB
__device__ u16 g_Plo [(size_t)NH * S_LEN * S_LEN];     // 256 MB
__device__ u16 g_Ahi [(size_t)S_LEN * HID];
__device__ u16 g_Alo [(size_t)S_LEN * HID];
__device__ u16 g_WqThi[(size_t)HID * HID];
__device__ u16 g_WqTlo[(size_t)HID * HID];
__device__ u16 g_WkThi[(size_t)HD * HID];
__device__ u16 g_WkTlo[(size_t)HD * HID];
__device__ u16 g_WvThi[(size_t)HD * HID];
__device__ u16 g_WvTlo[(size_t)HD * HID];
__device__ u16 g_WoThi[(size_t)HID * HID];
__device__ u16 g_WoTlo[(size_t)HID * HID];

// ------------------------- helpers ------------------------------------------
__device__ __forceinline__ void split_bf(float x, u16& h, u16& l) {
    __nv_bfloat16 hb = __float2bfloat16(x);
    float hf = __bfloat162float(hb);
    __nv_bfloat16 lb = __float2bfloat16(x - hf);
    h = __bfloat16_as_ushort(hb);
    l = __bfloat16_as_ushort(lb);
}
__device__ __forceinline__ uint32_t smem_u32(const void* p) {
    uint32_t a;
    asm("{ .reg .u64 t; cvta.to.shared.u64 t, %1; cvt.u32.u64 %0, t; }"
        : "=r"(a) : "l"(p));
    return a;
}
__device__ __forceinline__ void cpa16(uint32_t dst, const void* src) {
    asm volatile("cp.async.cg.shared.global [%0], [%1], 16;" :: "r"(dst), "l"(src));
}
__device__ __forceinline__ void cpa_commit() {
    asm volatile("cp.async.commit_group;");
}

#define LDSM4(r, a)                                                            \
    asm volatile("ldmatrix.sync.aligned.m8n8.x4.shared.b16 {%0,%1,%2,%3}, [%4];" \
        : "=r"((r)[0]), "=r"((r)[1]), "=r"((r)[2]), "=r"((r)[3]) : "r"(a))

#define MMA_BF16(acc, a, b)                                                    \
    asm volatile(                                                              \
        "mma.sync.aligned.m16n8k16.row.col.f32.bf16.bf16.f32 "                 \
        "{%0,%1,%2,%3},{%4,%5,%6,%7},{%8,%9},{%0,%1,%2,%3};"                   \
        : "+f"((acc)[0]), "+f"((acc)[1]), "+f"((acc)[2]), "+f"((acc)[3])       \
        : "r"((a)[0]), "r"((a)[1]), "r"((a)[2]), "r"((a)[3]),                  \
          "r"((b)[0]), "r"((b)[1]))

// ---------------------------------------------------------------------------
// bf16-split GEMM (NT): C[m,n] = alpha * sum_k A[m,k]*B[n,k]
// A,B given as separate hi/lo bf16 planes. CTA 128x128, K-chunk 32,
// 256 threads, 3-stage cp.async, ldmatrix fragment loads.
// SMEM rows: 32 bf16 data + 8 pad = 40 u16 (80 B) -> conflict-free LDSM.
// ---------------------------------------------------------------------------
#define TLH      40
#define PLANE_B  (128 * TLH * 2)     // 10240 B per plane tile
#define STAGE_B  (4 * PLANE_B)       // 40960 B
#define NSTAGE   3
#define GEMM_SMEM (NSTAGE * STAGE_B) // 122880 B

__global__ void __launch_bounds__(256, 1) bgemm(
    const u16* __restrict__ Ahi, const u16* __restrict__ Alo,
    const u16* __restrict__ Bhi, const u16* __restrict__ Blo,
    float* __restrict__ C,
    int K, int lda, int ldb, int ldc,
    long long sA, long long sB, long long sC, float alpha)
{
    extern __shared__ u16 smraw[];
    const uint32_t smb = smem_u32(smraw);

    const int tid  = threadIdx.x;
    const int wid  = tid >> 5;
    const int lane = tid & 31;
    const int g    = lane >> 2;
    const int tg   = lane & 3;
    const int wm   = (wid >> 2) * 64;
    const int wn   = (wid & 3) * 32;

    const int z  = blockIdx.z;
    const int m0 = blockIdx.y * 128;
    const int n0 = blockIdx.x * 128;
    const long long aoff = (long long)z * sA + (long long)m0 * lda;
    const long long boff = (long long)z * sB + (long long)n0 * ldb;
    const u16* gp0 = Ahi + aoff;
    const u16* gp1 = Alo + aoff;
    const u16* gp2 = Bhi + boff;
    const u16* gp3 = Blo + boff;
    C += (long long)z * sC;

    const int r_lo = tid >> 2;       // 0..63
    const int c16  = tid & 3;        // 16B granule in 64B row

    auto issue = [&](int c) {
        const uint32_t sbase = smb + (uint32_t)(c % NSTAGE) * STAGE_B;
        const int k0 = c << 5;
#pragma unroll
        for (int t = 0; t < 8; t++) {
            const int p   = t >> 1;
            const int row = ((t & 1) << 6) + r_lo;
            const u16* src = (p == 0) ? gp0 : (p == 1) ? gp1 : (p == 2) ? gp2 : gp3;
            const int ld   = (p < 2) ? lda : ldb;
            cpa16(sbase + (uint32_t)(p * PLANE_B + row * (TLH * 2) + c16 * 16),
                  src + (long long)row * ld + k0 + c16 * 8);
        }
        cpa_commit();
    };

    float acc[4][4][4];
#pragma unroll
    for (int i = 0; i < 4; i++)
#pragma unroll
        for (int j = 0; j < 4; j++)
#pragma unroll
            for (int r = 0; r < 4; r++) acc[i][j][r] = 0.0f;

    issue(0);
    issue(1);

    // ldmatrix per-lane address offsets
    const int l8 = lane & 7;
    const int lt = lane >> 3;
    const uint32_t a_lane = (uint32_t)((((lt & 1) << 3) + l8) * (TLH * 2) + ((lt >> 1) << 4));
    const uint32_t b_lane = (uint32_t)((((lt >> 1) << 3) + l8) * (TLH * 2) + ((lt & 1) << 4));

    const int nc = K >> 5;
    for (int c = 0; c < nc; c++) {
        if (c + 1 < nc) asm volatile("cp.async.wait_group 1;");
        else            asm volatile("cp.async.wait_group 0;");
        __syncthreads();
        if (c + 2 < nc) issue(c + 2);

        const uint32_t st  = smb + (uint32_t)(c % NSTAGE) * STAGE_B;
        const uint32_t aHi = st;
        const uint32_t aLo = st + PLANE_B;
        const uint32_t bHi = st + 2 * PLANE_B;
        const uint32_t bLo = st + 3 * PLANE_B;

#pragma unroll
        for (int ks = 0; ks < 2; ks++) {
            uint32_t ahi[4][4], alo[4][4], bhi[4][2], blo[4][2];
#pragma unroll
            for (int tm = 0; tm < 4; tm++) {
                const uint32_t base = (uint32_t)((wm + tm * 16) * (TLH * 2) + ks * 32);
                LDSM4(ahi[tm], aHi + base + a_lane);
                LDSM4(alo[tm], aLo + base + a_lane);
            }
#pragma unroll
            for (int j = 0; j < 2; j++) {
                const uint32_t base = (uint32_t)((wn + j * 16) * (TLH * 2) + ks * 32);
                uint32_t r[4];
                LDSM4(r, bHi + base + b_lane);
                bhi[2 * j][0] = r[0]; bhi[2 * j][1] = r[1];
                bhi[2 * j + 1][0] = r[2]; bhi[2 * j + 1][1] = r[3];
                LDSM4(r, bLo + base + b_lane);
                blo[2 * j][0] = r[0]; blo[2 * j][1] = r[1];
                blo[2 * j + 1][0] = r[2]; blo[2 * j + 1][1] = r[3];
            }
#pragma unroll
            for (int tm = 0; tm < 4; tm++)
#pragma unroll
                for (int tn = 0; tn < 4; tn++) MMA_BF16(acc[tm][tn], ahi[tm], bhi[tn]);
#pragma unroll
            for (int tm = 0; tm < 4; tm++)
#pragma unroll
                for (int tn = 0; tn < 4; tn++) MMA_BF16(acc[tm][tn], ahi[tm], blo[tn]);
#pragma unroll
            for (int tm = 0; tm < 4; tm++)
#pragma unroll
                for (int tn = 0; tn < 4; tn++) MMA_BF16(acc[tm][tn], alo[tm], bhi[tn]);
        }
        __syncthreads();
    }

    // epilogue
#pragma unroll
    for (int tm = 0; tm < 4; tm++) {
        const int row = m0 + wm + tm * 16 + g;
#pragma unroll
        for (int tn = 0; tn < 4; tn++) {
            const int col = n0 + wn + tn * 8 + 2 * tg;
            float2 lo, hi;
            lo.x = acc[tm][tn][0] * alpha; lo.y = acc[tm][tn][1] * alpha;
            hi.x = acc[tm][tn][2] * alpha; hi.y = acc[tm][tn][3] * alpha;
            *(float2*)(C + (long long)row * ldc + col) = lo;
            *(float2*)(C + (long long)(row + 8) * ldc + col) = hi;
        }
    }
}

// ---------------------------------------------------------------------------
// fp32 -> hi/lo plane pack (vector of 4)
// ---------------------------------------------------------------------------
__global__ void __launch_bounds__(256) pack_plane_kernel(
    const float* __restrict__ in, u16* __restrict__ oh, u16* __restrict__ ol,
    long long n4)
{
    const long long i = (long long)blockIdx.x * 256 + threadIdx.x;
    if (i >= n4) return;
    const float4 v = ((const float4*)in)[i];
    ushort4 h4, l4;
    split_bf(v.x, h4.x, l4.x); split_bf(v.y, h4.y, l4.y);
    split_bf(v.z, h4.z, l4.z); split_bf(v.w, h4.w, l4.w);
    ((ushort4*)oh)[i] = h4;
    ((ushort4*)ol)[i] = l4;
}

// ---------------------------------------------------------------------------
// Transpose + split: out[c][r] = split(in[r][c])
// ---------------------------------------------------------------------------
__device__ __forceinline__ void transpose_tile(
    const float* __restrict__ in, u16* __restrict__ oh, u16* __restrict__ ol,
    int R, int C, int bx, int by, int x, int y, float* tile /*32x33*/)
{
    const int c0 = bx * 32;
    const int r0 = by * 32;
#pragma unroll
    for (int i = 0; i < 32; i += 8)
        tile[(y + i) * 33 + x] = in[(long long)(r0 + y + i) * C + c0 + x];
    __syncthreads();
#pragma unroll
    for (int i = 0; i < 32; i += 8) {
        u16 h, l;
        split_bf(tile[x * 33 + y + i], h, l);
        const long long o = (long long)(c0 + y + i) * R + r0 + x;
        oh[o] = h; ol[o] = l;
    }
}

__global__ void __launch_bounds__(256) transpose_plane_kernel(
    const float* __restrict__ in, u16* __restrict__ oh, u16* __restrict__ ol,
    int R, int C)
{
    __shared__ float tile[32 * 33];
    transpose_tile(in, oh, ol, R, C, blockIdx.x, blockIdx.y,
                   threadIdx.x, threadIdx.y, tile);
}

// all 4 weight transposes in ONE launch (flattened grid)
__global__ void __launch_bounds__(256) transpose_weights_kernel(
    const float* __restrict__ Wq, const float* __restrict__ Wk,
    const float* __restrict__ Wv, const float* __restrict__ Wo,
    u16* __restrict__ qh, u16* __restrict__ ql,
    u16* __restrict__ kh, u16* __restrict__ kl,
    u16* __restrict__ vh, u16* __restrict__ vl,
    u16* __restrict__ oh, u16* __restrict__ ol)
{
    __shared__ float tile[32 * 33];
    const int b = blockIdx.x;
    const float* in; u16 *ph, *pl; int R, C, local;
    if (b < 4096)      { in = Wq; ph = qh; pl = ql; R = HID; C = HID; local = b; }
    else if (b < 4608) { in = Wk; ph = kh; pl = kl; R = HID; C = HD;  local = b - 4096; }
    else if (b < 5120) { in = Wv; ph = vh; pl = vl; R = HID; C = HD;  local = b - 4608; }
    else               { in = Wo; ph = oh; pl = ol; R = HID; C = HID; local = b - 5120; }
    const int tc = C / 32;
    transpose_tile(in, ph, pl, R, C, local % tc, local / tc,
                   threadIdx.x, threadIdx.y, tile);
}

// ---------------------------------------------------------------------------
// RoPE: fp32 g_Q/g_K -> hi/lo planes
// ---------------------------------------------------------------------------
__global__ void rope_pack_kernel(const int* __restrict__ pos_ids)
{
    const int s = blockIdx.x;
    const int j = threadIdx.x;           // 0..127
    const float p = (float)pos_ids[s];
    const float inv = expf(-((float)j * (1.0f / 128.0f)) * logf(10000.0f));
    const float ang = p * inv;
    const float c  = cosf(ang);
    const float sn = sinf(ang);

#pragma unroll
    for (int h = 0; h < NH; h++) {
        const size_t o = (size_t)s * HID + h * HD;
        const float x1 = g_Q[o + j];
        const float x2 = g_Q[o + j + 128];
        u16 hh, ll;
        split_bf(x1 * c - x2 * sn, hh, ll);
        g_Qhi[o + j] = hh; g_Qlo[o + j] = ll;
        split_bf(x2 * c + x1 * sn, hh, ll);
        g_Qhi[o + j + 128] = hh; g_Qlo[o + j + 128] = ll;
    }
    const size_t o = (size_t)s * HD;
    const float x1 = g_K[o + j];
    const float x2 = g_K[o + j + 128];
    u16 hh, ll;
    split_bf(x1 * c - x2 * sn, hh, ll);
    g_Khi[o + j] = hh; g_Klo[o + j] = ll;
    split_bf(x2 * c + x1 * sn, hh, ll);
    g_Khi[o + j + 128] = hh; g_Klo[o + j + 128] = ll;
}

// ---------------------------------------------------------------------------
// Softmax: one block per q row, all 8 heads; mask row staged in SMEM once.
// Writes P hi/lo planes.
// ---------------------------------------------------------------------------
__global__ void __launch_bounds__(256) softmax_kernel(const float* __restrict__ mask)
{
    const int q = blockIdx.x;
    const int tid = threadIdx.x;
    __shared__ float msk[S_LEN];
    __shared__ float red[256];

    const float* __restrict__ mrow = mask + (size_t)q * S_LEN;
#pragma unroll
    for (int i = 0; i < 16; i++) msk[tid + i * 256] = mrow[tid + i * 256];
    __syncthreads();

    for (int h = 0; h < NH; h++) {
        const size_t ro = ((size_t)h * S_LEN + q) * S_LEN;
        const float* __restrict__ row = g_S + ro;

        float v[16];
        float m = -1e30f;
#pragma unroll
        for (int i = 0; i < 16; i++) {
            const int k = tid + i * 256;
            v[i] = row[k] + msk[k];
            m = fmaxf(m, v[i]);
        }
        red[tid] = m;
        __syncthreads();
        for (int st = 128; st > 0; st >>= 1) {
            if (tid < st) red[tid] = fmaxf(red[tid], red[tid + st]);
            __syncthreads();
        }
        m = red[0];
        __syncthreads();

        float sum = 0.0f;
#pragma unroll
        for (int i = 0; i < 16; i++) {
            v[i] = __expf(v[i] - m);
            sum += v[i];
        }
        red[tid] = sum;
        __syncthreads();
        for (int st = 128; st > 0; st >>= 1) {
            if (tid < st) red[tid] += red[tid + st];
            __syncthreads();
        }
        const float inv = 1.0f / red[0];
        __syncthreads();   // allow red reuse next head

#pragma unroll
        for (int i = 0; i < 16; i++) {
            const int k = tid + i * 256;
            u16 hh, ll;
            split_bf(v[i] * inv, hh, ll);
            g_Phi[ro + k] = hh;
            g_Plo[ro + k] = ll;
        }
    }
}

// ---------------------------------------------------------------------------
// Launch.  Order arranged so launch #4 (ncu capture slot) = Q projection GEMM.
// ---------------------------------------------------------------------------
extern "C" void kernel_launch(void* const* d_in, const int* in_sizes, int n_in,
                              void* d_out, int out_size)
{
    const float* X    = (const float*)d_in[0];
    const float* mask = (const float*)d_in[1];
    const int*   pos  = (const int*)d_in[2];
    const float* Wq   = (const float*)d_in[3];
    const float* Wk   = (const float*)d_in[4];
    const float* Wv   = (const float*)d_in[5];
    const float* Wo   = (const float*)d_in[6];
    float* out = (float*)d_out;

    float *Q, *K, *V, *Sb, *A;
    u16 *Xhi,*Xlo,*Qhi,*Qlo,*Khi,*Klo,*VThi,*VTlo,*Phi,*Plo,*Ahi,*Alo;
    u16 *WqThi,*WqTlo,*WkThi,*WkTlo,*WvThi,*WvTlo,*WoThi,*WoTlo;
    cudaGetSymbolAddress((void**)&Q,   g_Q);
    cudaGetSymbolAddress((void**)&K,   g_K);
    cudaGetSymbolAddress((void**)&V,   g_V);
    cudaGetSymbolAddress((void**)&Sb,  g_S);
    cudaGetSymbolAddress((void**)&A,   g_A);
    cudaGetSymbolAddress((void**)&Xhi, g_Xhi);  cudaGetSymbolAddress((void**)&Xlo, g_Xlo);
    cudaGetSymbolAddress((void**)&Qhi, g_Qhi);  cudaGetSymbolAddress((void**)&Qlo, g_Qlo);
    cudaGetSymbolAddress((void**)&Khi, g_Khi);  cudaGetSymbolAddress((void**)&Klo, g_Klo);
    cudaGetSymbolAddress((void**)&VThi,g_VThi); cudaGetSymbolAddress((void**)&VTlo,g_VTlo);
    cudaGetSymbolAddress((void**)&Phi, g_Phi);  cudaGetSymbolAddress((void**)&Plo, g_Plo);
    cudaGetSymbolAddress((void**)&Ahi, g_Ahi);  cudaGetSymbolAddress((void**)&Alo, g_Alo);
    cudaGetSymbolAddress((void**)&WqThi,g_WqThi); cudaGetSymbolAddress((void**)&WqTlo,g_WqTlo);
    cudaGetSymbolAddress((void**)&WkThi,g_WkThi); cudaGetSymbolAddress((void**)&WkTlo,g_WkTlo);
    cudaGetSymbolAddress((void**)&WvThi,g_WvThi); cudaGetSymbolAddress((void**)&WvTlo,g_WvTlo);
    cudaGetSymbolAddress((void**)&WoThi,g_WoThi); cudaGetSymbolAddress((void**)&WoTlo,g_WoTlo);

    cudaFuncSetAttribute(bgemm, cudaFuncAttributeMaxDynamicSharedMemorySize, GEMM_SMEM);

    // 1: pack X
    pack_plane_kernel<<<(S_LEN * HID / 4 + 255) / 256, 256>>>(
        X, Xhi, Xlo, (long long)S_LEN * HID / 4);
    // 2: all weight transposes
    transpose_weights_kernel<<<9216, dim3(32, 8)>>>(
        Wq, Wk, Wv, Wo, WqThi, WqTlo, WkThi, WkTlo, WvThi, WvTlo, WoThi, WoTlo);
    // 3: K projection
    bgemm<<<dim3(HD / 128, S_LEN / 128, 1), 256, GEMM_SMEM>>>(
        Xhi, Xlo, WkThi, WkTlo, K, HID, HID, HID, HD, 0, 0, 0, 1.0f);
    // 4: Q projection  (ncu capture slot)
    bgemm<<<dim3(HID / 128, S_LEN / 128, 1), 256, GEMM_SMEM>>>(
        Xhi, Xlo, WqThi, WqTlo, Q, HID, HID, HID, HID, 0, 0, 0, 1.0f);
    // 5: V projection
    bgemm<<<dim3(HD / 128, S_LEN / 128, 1), 256, GEMM_SMEM>>>(
        Xhi, Xlo, WvThi, WvTlo, V, HID, HID, HID, HD, 0, 0, 0, 1.0f);
    // 6: RoPE -> packed planes
    rope_pack_kernel<<<S_LEN, 128>>>(pos);
    // 7: V^T planes
    transpose_plane_kernel<<<dim3(HD / 32, S_LEN / 32), dim3(32, 8)>>>(
        V, VThi, VTlo, S_LEN, HD);
    // 8: scores = (Q K^T)/16
    bgemm<<<dim3(S_LEN / 128, S_LEN / 128, NH), 256, GEMM_SMEM>>>(
        Qhi, Qlo, Khi, Klo, Sb, HD, HID, HD, S_LEN,
        (long long)HD, 0, (long long)S_LEN * S_LEN, 1.0f / 16.0f);
    // 9: softmax -> P planes
    softmax_kernel<<<S_LEN, 256>>>(mask);
    // 10: A = P @ V
    bgemm<<<dim3(HD / 128, S_LEN / 128, NH), 256, GEMM_SMEM>>>(
        Phi, Plo, VThi, VTlo, A, S_LEN, S_LEN, S_LEN, HID,
        (long long)S_LEN * S_LEN, 0, (long long)HD, 1.0f);
    // 11: pack A
    pack_plane_kernel<<<(S_LEN * HID / 4 + 255) / 256, 256>>>(
        A, Ahi, Alo, (long long)S_LEN * HID / 4);
    // 12: out = A @ Wo
    bgemm<<<dim3(HID / 128, S_LEN / 128, 1), 256, GEMM_SMEM>>>(
        Ahi, Alo, WoThi, WoTlo, out, HID, HID, HID, HID, 0, 0, 0, 1.0f);
}

// round 6
// speedup vs baseline: 1.1186x; 1.1186x over previous
#include <cuda_runtime.h>
#include <cuda_bf16.h>
#include <math.h>
#include <cstdint>

#define S_LEN 4096
#define HID   2048
#define NH    8
#define HD    256

typedef unsigned short u16;

// ------------------------- device scratch (no allocs allowed) ---------------
__device__ float g_Q [(size_t)S_LEN * HID];
__device__ float g_K [(size_t)S_LEN * HD];
__device__ float g_V [(size_t)S_LEN * HD];
__device__ float g_S [(size_t)NH * S_LEN * S_LEN];     // fp32 scores
__device__ float g_A [(size_t)S_LEN * HID];

__device__ u16 g_Xhi [(size_t)S_LEN * HID];
__device__ u16 g_Xlo [(size_t)S_LEN * HID];
__device__ u16 g_Qhi [(size_t)S_LEN * HID];
__device__ u16 g_Qlo [(size_t)S_LEN * HID];
__device__ u16 g_Khi [(size_t)S_LEN * HD];
__device__ u16 g_Klo [(size_t)S_LEN * HD];
__device__ u16 g_VThi[(size_t)HD * S_LEN];
__device__ u16 g_VTlo[(size_t)HD * S_LEN];
__device__ u16 g_Phi [(size_t)NH * S_LEN * S_LEN];
__device__ u16 g_Plo [(size_t)NH * S_LEN * S_LEN];
__device__ u16 g_Ahi [(size_t)S_LEN * HID];
__device__ u16 g_Alo [(size_t)S_LEN * HID];
__device__ u16 g_WqThi[(size_t)HID * HID];
__device__ u16 g_WqTlo[(size_t)HID * HID];
__device__ u16 g_WkThi[(size_t)HD * HID];
__device__ u16 g_WkTlo[(size_t)HD * HID];
__device__ u16 g_WvThi[(size_t)HD * HID];
__device__ u16 g_WvTlo[(size_t)HD * HID];
__device__ u16 g_WoThi[(size_t)HID * HID];
__device__ u16 g_WoTlo[(size_t)HID * HID];

// ------------------------- helpers ------------------------------------------
__device__ __forceinline__ void split_bf(float x, u16& h, u16& l) {
    __nv_bfloat16 hb = __float2bfloat16(x);
    float hf = __bfloat162float(hb);
    __nv_bfloat16 lb = __float2bfloat16(x - hf);
    h = __bfloat16_as_ushort(hb);
    l = __bfloat16_as_ushort(lb);
}
__device__ __forceinline__ uint32_t smem_u32(const void* p) {
    uint32_t a;
    asm("{ .reg .u64 t; cvta.to.shared.u64 t, %1; cvt.u32.u64 %0, t; }"
        : "=r"(a) : "l"(p));
    return a;
}
__device__ __forceinline__ void cpa16(uint32_t dst, const void* src) {
    asm volatile("cp.async.cg.shared.global [%0], [%1], 16;" :: "r"(dst), "l"(src));
}
__device__ __forceinline__ void cpa_commit() {
    asm volatile("cp.async.commit_group;");
}

#define LDSM4(r, a)                                                            \
    asm volatile("ldmatrix.sync.aligned.m8n8.x4.shared.b16 {%0,%1,%2,%3}, [%4];" \
        : "=r"((r)[0]), "=r"((r)[1]), "=r"((r)[2]), "=r"((r)[3]) : "r"(a))

#define MMA_BF16(acc, a, b)                                                    \
    asm volatile(                                                              \
        "mma.sync.aligned.m16n8k16.row.col.f32.bf16.bf16.f32 "                 \
        "{%0,%1,%2,%3},{%4,%5,%6,%7},{%8,%9},{%0,%1,%2,%3};"                   \
        : "+f"((acc)[0]), "+f"((acc)[1]), "+f"((acc)[2]), "+f"((acc)[3])       \
        : "r"((a)[0]), "r"((a)[1]), "r"((a)[2]), "r"((a)[3]),                  \
          "r"((b)[0]), "r"((b)[1]))

// ---------------------------------------------------------------------------
// bf16-split GEMM (NT): C[m,n] = alpha * sum_k A[m,k]*B[n,k]
// CTA 128x128, K-chunk 32, 256 threads, 2-stage cp.async, 2 CTAs/SM.
// SMEM rows: 32 bf16 + 8 pad = 40 u16 (80 B) -> conflict-free LDSM.
// ---------------------------------------------------------------------------
#define TLH      40
#define PLANE_B  (128 * TLH * 2)     // 10240 B per plane tile
#define STAGE_B  (4 * PLANE_B)       // 40960 B
#define NSTAGE   2
#define GEMM_SMEM (NSTAGE * STAGE_B) // 81920 B

__global__ void __launch_bounds__(256, 2) bgemm(
    const u16* __restrict__ Ahi, const u16* __restrict__ Alo,
    const u16* __restrict__ Bhi, const u16* __restrict__ Blo,
    float* __restrict__ C,
    int K, int lda, int ldb, int ldc,
    long long sA, long long sB, long long sC, float alpha)
{
    extern __shared__ u16 smraw[];
    const uint32_t smb = smem_u32(smraw);

    const int tid  = threadIdx.x;
    const int wid  = tid >> 5;
    const int lane = tid & 31;
    const int g    = lane >> 2;
    const int tg   = lane & 3;
    const int wm   = (wid >> 2) * 64;
    const int wn   = (wid & 3) * 32;

    const int z  = blockIdx.z;
    const int m0 = blockIdx.y * 128;
    const int n0 = blockIdx.x * 128;
    const long long aoff = (long long)z * sA + (long long)m0 * lda;
    const long long boff = (long long)z * sB + (long long)n0 * ldb;
    const u16* gp0 = Ahi + aoff;
    const u16* gp1 = Alo + aoff;
    const u16* gp2 = Bhi + boff;
    const u16* gp3 = Blo + boff;
    C += (long long)z * sC;

    const int r_lo = tid >> 2;       // 0..63
    const int c16  = tid & 3;        // 16B granule in 64B row

    auto issue = [&](int c) {
        const uint32_t sbase = smb + (uint32_t)(c % NSTAGE) * STAGE_B;
        const int k0 = c << 5;
#pragma unroll
        for (int t = 0; t < 8; t++) {
            const int p   = t >> 1;
            const int row = ((t & 1) << 6) + r_lo;
            const u16* src = (p == 0) ? gp0 : (p == 1) ? gp1 : (p == 2) ? gp2 : gp3;
            const int ld   = (p < 2) ? lda : ldb;
            cpa16(sbase + (uint32_t)(p * PLANE_B + row * (TLH * 2) + c16 * 16),
                  src + (long long)row * ld + k0 + c16 * 8);
        }
        cpa_commit();
    };

    float acc[4][4][4];
#pragma unroll
    for (int i = 0; i < 4; i++)
#pragma unroll
        for (int j = 0; j < 4; j++)
#pragma unroll
            for (int r = 0; r < 4; r++) acc[i][j][r] = 0.0f;

    issue(0);
    issue(1);

    // ldmatrix per-lane address offsets
    const int l8 = lane & 7;
    const int lt = lane >> 3;
    const uint32_t a_lane = (uint32_t)((((lt & 1) << 3) + l8) * (TLH * 2) + ((lt >> 1) << 4));
    const uint32_t b_lane = (uint32_t)((((lt >> 1) << 3) + l8) * (TLH * 2) + ((lt & 1) << 4));

    const int nc = K >> 5;
    for (int c = 0; c < nc; c++) {
        if (c + 1 < nc) asm volatile("cp.async.wait_group 1;");
        else            asm volatile("cp.async.wait_group 0;");
        __syncthreads();

        const uint32_t st  = smb + (uint32_t)(c % NSTAGE) * STAGE_B;
        const uint32_t aHi = st;
        const uint32_t aLo = st + PLANE_B;
        const uint32_t bHi = st + 2 * PLANE_B;
        const uint32_t bLo = st + 3 * PLANE_B;

#pragma unroll
        for (int ks = 0; ks < 2; ks++) {
            uint32_t bhi[4][2], blo[4][2];
#pragma unroll
            for (int j = 0; j < 2; j++) {
                const uint32_t base = (uint32_t)((wn + j * 16) * (TLH * 2) + ks * 32);
                uint32_t r[4];
                LDSM4(r, bHi + base + b_lane);
                bhi[2 * j][0] = r[0]; bhi[2 * j][1] = r[1];
                bhi[2 * j + 1][0] = r[2]; bhi[2 * j + 1][1] = r[3];
                LDSM4(r, bLo + base + b_lane);
                blo[2 * j][0] = r[0]; blo[2 * j][1] = r[1];
                blo[2 * j + 1][0] = r[2]; blo[2 * j + 1][1] = r[3];
            }
#pragma unroll
            for (int tm = 0; tm < 4; tm++) {
                const uint32_t base = (uint32_t)((wm + tm * 16) * (TLH * 2) + ks * 32);
                uint32_t ahi[4], alo[4];
                LDSM4(ahi, aHi + base + a_lane);
                LDSM4(alo, aLo + base + a_lane);
#pragma unroll
                for (int tn = 0; tn < 4; tn++) MMA_BF16(acc[tm][tn], ahi, bhi[tn]);
#pragma unroll
                for (int tn = 0; tn < 4; tn++) MMA_BF16(acc[tm][tn], ahi, blo[tn]);
#pragma unroll
                for (int tn = 0; tn < 4; tn++) MMA_BF16(acc[tm][tn], alo, bhi[tn]);
            }
        }
        __syncthreads();
        if (c + 2 < nc) issue(c + 2);
    }

    // epilogue
#pragma unroll
    for (int tm = 0; tm < 4; tm++) {
        const int row = m0 + wm + tm * 16 + g;
#pragma unroll
        for (int tn = 0; tn < 4; tn++) {
            const int col = n0 + wn + tn * 8 + 2 * tg;
            float2 lo, hi;
            lo.x = acc[tm][tn][0] * alpha; lo.y = acc[tm][tn][1] * alpha;
            hi.x = acc[tm][tn][2] * alpha; hi.y = acc[tm][tn][3] * alpha;
            *(float2*)(C + (long long)row * ldc + col) = lo;
            *(float2*)(C + (long long)(row + 8) * ldc + col) = hi;
        }
    }
}

// ---------------------------------------------------------------------------
// fp32 -> hi/lo plane pack (vector of 4)
// ---------------------------------------------------------------------------
__global__ void __launch_bounds__(256) pack_plane_kernel(
    const float* __restrict__ in, u16* __restrict__ oh, u16* __restrict__ ol,
    long long n4)
{
    const long long i = (long long)blockIdx.x * 256 + threadIdx.x;
    if (i >= n4) return;
    const float4 v = ((const float4*)in)[i];
    ushort4 h4, l4;
    split_bf(v.x, h4.x, l4.x); split_bf(v.y, h4.y, l4.y);
    split_bf(v.z, h4.z, l4.z); split_bf(v.w, h4.w, l4.w);
    ((ushort4*)oh)[i] = h4;
    ((ushort4*)ol)[i] = l4;
}

// ---------------------------------------------------------------------------
// Transpose + split: out[c][r] = split(in[r][c])
// ---------------------------------------------------------------------------
__device__ __forceinline__ void transpose_tile(
    const float* __restrict__ in, u16* __restrict__ oh, u16* __restrict__ ol,
    int R, int C, int bx, int by, int x, int y, float* tile /*32x33*/)
{
    const int c0 = bx * 32;
    const int r0 = by * 32;
#pragma unroll
    for (int i = 0; i < 32; i += 8)
        tile[(y + i) * 33 + x] = in[(long long)(r0 + y + i) * C + c0 + x];
    __syncthreads();
#pragma unroll
    for (int i = 0; i < 32; i += 8) {
        u16 h, l;
        split_bf(tile[x * 33 + y + i], h, l);
        const long long o = (long long)(c0 + y + i) * R + r0 + x;
        oh[o] = h; ol[o] = l;
    }
}

__global__ void __launch_bounds__(256) transpose_plane_kernel(
    const float* __restrict__ in, u16* __restrict__ oh, u16* __restrict__ ol,
    int R, int C)
{
    __shared__ float tile[32 * 33];
    transpose_tile(in, oh, ol, R, C, blockIdx.x, blockIdx.y,
                   threadIdx.x, threadIdx.y, tile);
}

// all 4 weight transposes in ONE launch (flattened grid)
__global__ void __launch_bounds__(256) transpose_weights_kernel(
    const float* __restrict__ Wq, const float* __restrict__ Wk,
    const float* __restrict__ Wv, const float* __restrict__ Wo,
    u16* __restrict__ qh, u16* __restrict__ ql,
    u16* __restrict__ kh, u16* __restrict__ kl,
    u16* __restrict__ vh, u16* __restrict__ vl,
    u16* __restrict__ oh, u16* __restrict__ ol)
{
    __shared__ float tile[32 * 33];
    const int b = blockIdx.x;
    const float* in; u16 *ph, *pl; int R, C, local;
    if (b < 4096)      { in = Wq; ph = qh; pl = ql; R = HID; C = HID; local = b; }
    else if (b < 4608) { in = Wk; ph = kh; pl = kl; R = HID; C = HD;  local = b - 4096; }
    else if (b < 5120) { in = Wv; ph = vh; pl = vl; R = HID; C = HD;  local = b - 4608; }
    else               { in = Wo; ph = oh; pl = ol; R = HID; C = HID; local = b - 5120; }
    const int tc = C / 32;
    transpose_tile(in, ph, pl, R, C, local % tc, local / tc,
                   threadIdx.x, threadIdx.y, tile);
}

// ---------------------------------------------------------------------------
// RoPE: fp32 g_Q/g_K -> hi/lo planes
// ---------------------------------------------------------------------------
__global__ void rope_pack_kernel(const int* __restrict__ pos_ids)
{
    const int s = blockIdx.x;
    const int j = threadIdx.x;           // 0..127
    const float p = (float)pos_ids[s];
    const float inv = expf(-((float)j * (1.0f / 128.0f)) * logf(10000.0f));
    const float ang = p * inv;
    const float c  = cosf(ang);
    const float sn = sinf(ang);

#pragma unroll
    for (int h = 0; h < NH; h++) {
        const size_t o = (size_t)s * HID + h * HD;
        const float x1 = g_Q[o + j];
        const float x2 = g_Q[o + j + 128];
        u16 hh, ll;
        split_bf(x1 * c - x2 * sn, hh, ll);
        g_Qhi[o + j] = hh; g_Qlo[o + j] = ll;
        split_bf(x2 * c + x1 * sn, hh, ll);
        g_Qhi[o + j + 128] = hh; g_Qlo[o + j + 128] = ll;
    }
    const size_t o = (size_t)s * HD;
    const float x1 = g_K[o + j];
    const float x2 = g_K[o + j + 128];
    u16 hh, ll;
    split_bf(x1 * c - x2 * sn, hh, ll);
    g_Khi[o + j] = hh; g_Klo[o + j] = ll;
    split_bf(x2 * c + x1 * sn, hh, ll);
    g_Khi[o + j + 128] = hh; g_Klo[o + j + 128] = ll;
}

// ---------------------------------------------------------------------------
// Softmax: one block per q row, all 8 heads; mask row staged in SMEM once.
// ---------------------------------------------------------------------------
__global__ void __launch_bounds__(256) softmax_kernel(const float* __restrict__ mask)
{
    const int q = blockIdx.x;
    const int tid = threadIdx.x;
    __shared__ float msk[S_LEN];
    __shared__ float red[256];

    const float* __restrict__ mrow = mask + (size_t)q * S_LEN;
#pragma unroll
    for (int i = 0; i < 16; i++) msk[tid + i * 256] = mrow[tid + i * 256];
    __syncthreads();

    for (int h = 0; h < NH; h++) {
        const size_t ro = ((size_t)h * S_LEN + q) * S_LEN;
        const float* __restrict__ row = g_S + ro;

        float v[16];
        float m = -1e30f;
#pragma unroll
        for (int i = 0; i < 16; i++) {
            const int k = tid + i * 256;
            v[i] = row[k] + msk[k];
            m = fmaxf(m, v[i]);
        }
        red[tid] = m;
        __syncthreads();
        for (int st = 128; st > 0; st >>= 1) {
            if (tid < st) red[tid] = fmaxf(red[tid], red[tid + st]);
            __syncthreads();
        }
        m = red[0];
        __syncthreads();

        float sum = 0.0f;
#pragma unroll
        for (int i = 0; i < 16; i++) {
            v[i] = __expf(v[i] - m);
            sum += v[i];
        }
        red[tid] = sum;
        __syncthreads();
        for (int st = 128; st > 0; st >>= 1) {
            if (tid < st) red[tid] += red[tid + st];
            __syncthreads();
        }
        const float inv = 1.0f / red[0];
        __syncthreads();

#pragma unroll
        for (int i = 0; i < 16; i++) {
            const int k = tid + i * 256;
            u16 hh, ll;
            split_bf(v[i] * inv, hh, ll);
            g_Phi[ro + k] = hh;
            g_Plo[ro + k] = ll;
        }
    }
}

// ---------------------------------------------------------------------------
// Launch.  Order keeps launch #4 (ncu capture slot) = Q projection GEMM.
// ---------------------------------------------------------------------------
extern "C" void kernel_launch(void* const* d_in, const int* in_sizes, int n_in,
                              void* d_out, int out_size)
{
    const float* X    = (const float*)d_in[0];
    const float* mask = (const float*)d_in[1];
    const int*   pos  = (const int*)d_in[2];
    const float* Wq   = (const float*)d_in[3];
    const float* Wk   = (const float*)d_in[4];
    const float* Wv   = (const float*)d_in[5];
    const float* Wo   = (const float*)d_in[6];
    float* out = (float*)d_out;

    float *Q, *K, *V, *Sb, *A;
    u16 *Xhi,*Xlo,*Qhi,*Qlo,*Khi,*Klo,*VThi,*VTlo,*Phi,*Plo,*Ahi,*Alo;
    u16 *WqThi,*WqTlo,*WkThi,*WkTlo,*WvThi,*WvTlo,*WoThi,*WoTlo;
    cudaGetSymbolAddress((void**)&Q,   g_Q);
    cudaGetSymbolAddress((void**)&K,   g_K);
    cudaGetSymbolAddress((void**)&V,   g_V);
    cudaGetSymbolAddress((void**)&Sb,  g_S);
    cudaGetSymbolAddress((void**)&A,   g_A);
    cudaGetSymbolAddress((void**)&Xhi, g_Xhi);  cudaGetSymbolAddress((void**)&Xlo, g_Xlo);
    cudaGetSymbolAddress((void**)&Qhi, g_Qhi);  cudaGetSymbolAddress((void**)&Qlo, g_Qlo);
    cudaGetSymbolAddress((void**)&Khi, g_Khi);  cudaGetSymbolAddress((void**)&Klo, g_Klo);
    cudaGetSymbolAddress((void**)&VThi,g_VThi); cudaGetSymbolAddress((void**)&VTlo,g_VTlo);
    cudaGetSymbolAddress((void**)&Phi, g_Phi);  cudaGetSymbolAddress((void**)&Plo, g_Plo);
    cudaGetSymbolAddress((void**)&Ahi, g_Ahi);  cudaGetSymbolAddress((void**)&Alo, g_Alo);
    cudaGetSymbolAddress((void**)&WqThi,g_WqThi); cudaGetSymbolAddress((void**)&WqTlo,g_WqTlo);
    cudaGetSymbolAddress((void**)&WkThi,g_WkThi); cudaGetSymbolAddress((void**)&WkTlo,g_WkTlo);
    cudaGetSymbolAddress((void**)&WvThi,g_WvThi); cudaGetSymbolAddress((void**)&WvTlo,g_WvTlo);
    cudaGetSymbolAddress((void**)&WoThi,g_WoThi); cudaGetSymbolAddress((void**)&WoTlo,g_WoTlo);

    cudaFuncSetAttribute(bgemm, cudaFuncAttributeMaxDynamicSharedMemorySize, GEMM_SMEM);

    // 1: pack X
    pack_plane_kernel<<<(S_LEN * HID / 4 + 255) / 256, 256>>>(
        X, Xhi, Xlo, (long long)S_LEN * HID / 4);
    // 2: all weight transposes
    transpose_weights_kernel<<<9216, dim3(32, 8)>>>(
        Wq, Wk, Wv, Wo, WqThi, WqTlo, WkThi, WkTlo, WvThi, WvTlo, WoThi, WoTlo);
    // 3: K projection
    bgemm<<<dim3(HD / 128, S_LEN / 128, 1), 256, GEMM_SMEM>>>(
        Xhi, Xlo, WkThi, WkTlo, K, HID, HID, HID, HD, 0, 0, 0, 1.0f);
    // 4: Q projection  (ncu capture slot)
    bgemm<<<dim3(HID / 128, S_LEN / 128, 1), 256, GEMM_SMEM>>>(
        Xhi, Xlo, WqThi, WqTlo, Q, HID, HID, HID, HID, 0, 0, 0, 1.0f);
    // 5: V projection
    bgemm<<<dim3(HD / 128, S_LEN / 128, 1), 256, GEMM_SMEM>>>(
        Xhi, Xlo, WvThi, WvTlo, V, HID, HID, HID, HD, 0, 0, 0, 1.0f);
    // 6: RoPE -> packed planes
    rope_pack_kernel<<<S_LEN, 128>>>(pos);
    // 7: V^T planes
    transpose_plane_kernel<<<dim3(HD / 32, S_LEN / 32), dim3(32, 8)>>>(
        V, VThi, VTlo, S_LEN, HD);
    // 8: scores = (Q K^T)/16
    bgemm<<<dim3(S_LEN / 128, S_LEN / 128, NH), 256, GEMM_SMEM>>>(
        Qhi, Qlo, Khi, Klo, Sb, HD, HID, HD, S_LEN,
        (long long)HD, 0, (long long)S_LEN * S_LEN, 1.0f / 16.0f);
    // 9: softmax -> P planes
    softmax_kernel<<<S_LEN, 256>>>(mask);
    // 10: A = P @ V
    bgemm<<<dim3(HD / 128, S_LEN / 128, NH), 256, GEMM_SMEM>>>(
        Phi, Plo, VThi, VTlo, A, S_LEN, S_LEN, S_LEN, HID,
        (long long)S_LEN * S_LEN, 0, (long long)HD, 1.0f);
    // 11: pack A
    pack_plane_kernel<<<(S_LEN * HID / 4 + 255) / 256, 256>>>(
        A, Ahi, Alo, (long long)S_LEN * HID / 4);
    // 12: out = A @ Wo
    bgemm<<<dim3(HID / 128, S_LEN / 128, 1), 256, GEMM_SMEM>>>(
        Ahi, Alo, WoThi, WoTlo, out, HID, HID, HID, HID, 0, 0, 0, 1.0f);
}

// round 7
// speedup vs baseline: 1.2458x; 1.1138x over previous
#include <cuda_runtime.h>
#include <cuda_bf16.h>
#include <math.h>
#include <cstdint>

#define S_LEN 4096
#define HID   2048
#define NH    8
#define HD    256

typedef unsigned short u16;

// ------------------------- device scratch (no allocs allowed) ---------------
__device__ float g_Q [(size_t)S_LEN * HID];
__device__ float g_K [(size_t)S_LEN * HD];
__device__ float g_V [(size_t)S_LEN * HD];
__device__ float g_S [(size_t)NH * S_LEN * S_LEN];     // fp32 scores
__device__ float g_A [(size_t)S_LEN * HID];

__device__ u16 g_Xhi [(size_t)S_LEN * HID];
__device__ u16 g_Xlo [(size_t)S_LEN * HID];
__device__ u16 g_Qhi [(size_t)S_LEN * HID];
__device__ u16 g_Qlo [(size_t)S_LEN * HID];
__device__ u16 g_Khi [(size_t)S_LEN * HD];
__device__ u16 g_Klo [(size_t)S_LEN * HD];
__device__ u16 g_VThi[(size_t)HD * S_LEN];
__device__ u16 g_VTlo[(size_t)HD * S_LEN];
__device__ u16 g_Phi [(size_t)NH * S_LEN * S_LEN];
__device__ u16 g_Plo [(size_t)NH * S_LEN * S_LEN];
__device__ u16 g_Ahi [(size_t)S_LEN * HID];
__device__ u16 g_Alo [(size_t)S_LEN * HID];
__device__ u16 g_WqThi[(size_t)HID * HID];
__device__ u16 g_WqTlo[(size_t)HID * HID];
__device__ u16 g_WkThi[(size_t)HD * HID];
__device__ u16 g_WkTlo[(size_t)HD * HID];
__device__ u16 g_WvThi[(size_t)HD * HID];
__device__ u16 g_WvTlo[(size_t)HD * HID];
__device__ u16 g_WoThi[(size_t)HID * HID];
__device__ u16 g_WoTlo[(size_t)HID * HID];

// ------------------------- helpers ------------------------------------------
__device__ __forceinline__ void split_bf(float x, u16& h, u16& l) {
    __nv_bfloat16 hb = __float2bfloat16(x);
    float hf = __bfloat162float(hb);
    __nv_bfloat16 lb = __float2bfloat16(x - hf);
    h = __bfloat16_as_ushort(hb);
    l = __bfloat16_as_ushort(lb);
}
__device__ __forceinline__ uint32_t smem_u32(const void* p) {
    uint32_t a;
    asm("{ .reg .u64 t; cvta.to.shared.u64 t, %1; cvt.u32.u64 %0, t; }"
        : "=r"(a) : "l"(p));
    return a;
}
__device__ __forceinline__ void cpa16(uint32_t dst, const void* src) {
    asm volatile("cp.async.cg.shared.global [%0], [%1], 16;" :: "r"(dst), "l"(src));
}
__device__ __forceinline__ void cpa_commit() {
    asm volatile("cp.async.commit_group;");
}

#define LDSM4(r, a)                                                            \
    asm volatile("ldmatrix.sync.aligned.m8n8.x4.shared.b16 {%0,%1,%2,%3}, [%4];" \
        : "=r"((r)[0]), "=r"((r)[1]), "=r"((r)[2]), "=r"((r)[3]) : "r"(a))

#define MMA_BF16(acc, a, b)                                                    \
    asm volatile(                                                              \
        "mma.sync.aligned.m16n8k16.row.col.f32.bf16.bf16.f32 "                 \
        "{%0,%1,%2,%3},{%4,%5,%6,%7},{%8,%9},{%0,%1,%2,%3};"                   \
        : "+f"((acc)[0]), "+f"((acc)[1]), "+f"((acc)[2]), "+f"((acc)[3])       \
        : "r"((a)[0]), "r"((a)[1]), "r"((a)[2]), "r"((a)[3]),                  \
          "r"((b)[0]), "r"((b)[1]))

// ---------------------------------------------------------------------------
// bf16-split GEMM (NT): C[m,n] = alpha * sum_k A[m,k]*B[n,k]
// CTA 128x128, K-chunk 32, 256 threads, 3 SMEM buffers / 2 in-flight cp.async
// groups, ONE __syncthreads per chunk, 2 CTAs/SM.
// SMEM rows: 32 u16 = 64 B, XOR swizzle (g' = g ^ ((row>>1)&3)) -> no pad,
// conflict-free for ldmatrix phases and cp.async stores.
// ---------------------------------------------------------------------------
#define PLANE_B  (128 * 64)          // 8192 B per plane tile
#define STAGE_B  (4 * PLANE_B)       // 32768 B
#define GEMM_SMEM (3 * STAGE_B)      // 98304 B

__global__ void __launch_bounds__(256, 2) bgemm(
    const u16* __restrict__ Ahi, const u16* __restrict__ Alo,
    const u16* __restrict__ Bhi, const u16* __restrict__ Blo,
    float* __restrict__ C,
    int K, int lda, int ldb, int ldc,
    long long sA, long long sB, long long sC, float alpha)
{
    extern __shared__ u16 smraw[];
    const uint32_t smb = smem_u32(smraw);

    const int tid  = threadIdx.x;
    const int wid  = tid >> 5;
    const int lane = tid & 31;
    const int g    = lane >> 2;
    const int tg   = lane & 3;
    const int wm   = (wid >> 2) * 64;
    const int wn   = (wid & 3) * 32;

    const int z  = blockIdx.z;
    const int m0 = blockIdx.y * 128;
    const int n0 = blockIdx.x * 128;
    const long long aoff = (long long)z * sA + (long long)m0 * lda;
    const long long boff = (long long)z * sB + (long long)n0 * ldb;
    const u16* gp0 = Ahi + aoff;
    const u16* gp1 = Alo + aoff;
    const u16* gp2 = Bhi + boff;
    const u16* gp3 = Blo + boff;
    C += (long long)z * sC;

    const int r_lo = tid >> 2;       // 0..63
    const int c16  = tid & 3;        // 16B granule in 64B row

    auto issue = [&](int c) {
        const uint32_t sbase = smb + (uint32_t)(c % 3) * STAGE_B;
        const int k0 = c << 5;
#pragma unroll
        for (int t = 0; t < 8; t++) {
            const int p   = t >> 1;
            const int row = ((t & 1) << 6) + r_lo;
            const int gsw = c16 ^ ((row >> 1) & 3);
            const u16* src = (p == 0) ? gp0 : (p == 1) ? gp1 : (p == 2) ? gp2 : gp3;
            const int ld   = (p < 2) ? lda : ldb;
            cpa16(sbase + (uint32_t)(p * PLANE_B + row * 64 + (gsw << 4)),
                  src + (long long)row * ld + k0 + c16 * 8);
        }
        cpa_commit();
    };

    float acc[4][4][4];
#pragma unroll
    for (int i = 0; i < 4; i++)
#pragma unroll
        for (int j = 0; j < 4; j++)
#pragma unroll
            for (int r = 0; r < 4; r++) acc[i][j][r] = 0.0f;

    // per-lane fragment offsets (within a plane), precomputed per tm/j/ks
    const int l8 = lane & 7;
    const int lt = lane >> 3;
    const int rA = ((lt & 1) << 3) + l8;    // row within 16-row block (A)
    const int gA = lt >> 1;                 // granule within k16 (A)
    const int rB = ((lt >> 1) << 3) + l8;   // row within 16-row block (B)
    const int gB = lt & 1;                  // granule within k16 (B)

    uint32_t offA[4][2], offB[2][2];
#pragma unroll
    for (int tm = 0; tm < 4; tm++) {
        const int R = wm + tm * 16 + rA;
        const int sw = (R >> 1) & 3;
#pragma unroll
        for (int ks = 0; ks < 2; ks++)
            offA[tm][ks] = (uint32_t)(R * 64 + (((ks * 2 + gA) ^ sw) << 4));
    }
#pragma unroll
    for (int j = 0; j < 2; j++) {
        const int R = wn + j * 16 + rB;
        const int sw = (R >> 1) & 3;
#pragma unroll
        for (int ks = 0; ks < 2; ks++)
            offB[j][ks] = (uint32_t)(R * 64 + (((ks * 2 + gB) ^ sw) << 4));
    }

    issue(0);
    issue(1);

    const int nc = K >> 5;
    for (int c = 0; c < nc; c++) {
        if (c < nc - 1) asm volatile("cp.async.wait_group 1;");
        else            asm volatile("cp.async.wait_group 0;");
        __syncthreads();
        if (c + 2 < nc) issue(c + 2);

        const uint32_t st  = smb + (uint32_t)(c % 3) * STAGE_B;
        const uint32_t aHi = st;
        const uint32_t aLo = st + PLANE_B;
        const uint32_t bHi = st + 2 * PLANE_B;
        const uint32_t bLo = st + 3 * PLANE_B;

#pragma unroll
        for (int ks = 0; ks < 2; ks++) {
            uint32_t bhi[4][2], blo[4][2];
#pragma unroll
            for (int j = 0; j < 2; j++) {
                uint32_t r[4];
                LDSM4(r, bHi + offB[j][ks]);
                bhi[2 * j][0] = r[0]; bhi[2 * j][1] = r[1];
                bhi[2 * j + 1][0] = r[2]; bhi[2 * j + 1][1] = r[3];
                LDSM4(r, bLo + offB[j][ks]);
                blo[2 * j][0] = r[0]; blo[2 * j][1] = r[1];
                blo[2 * j + 1][0] = r[2]; blo[2 * j + 1][1] = r[3];
            }
#pragma unroll
            for (int tm = 0; tm < 4; tm++) {
                uint32_t ahi[4], alo[4];
                LDSM4(ahi, aHi + offA[tm][ks]);
                LDSM4(alo, aLo + offA[tm][ks]);
#pragma unroll
                for (int tn = 0; tn < 4; tn++) MMA_BF16(acc[tm][tn], ahi, bhi[tn]);
#pragma unroll
                for (int tn = 0; tn < 4; tn++) MMA_BF16(acc[tm][tn], ahi, blo[tn]);
#pragma unroll
                for (int tn = 0; tn < 4; tn++) MMA_BF16(acc[tm][tn], alo, bhi[tn]);
            }
        }
    }

    // epilogue
#pragma unroll
    for (int tm = 0; tm < 4; tm++) {
        const int row = m0 + wm + tm * 16 + g;
#pragma unroll
        for (int tn = 0; tn < 4; tn++) {
            const int col = n0 + wn + tn * 8 + 2 * tg;
            float2 lo, hi;
            lo.x = acc[tm][tn][0] * alpha; lo.y = acc[tm][tn][1] * alpha;
            hi.x = acc[tm][tn][2] * alpha; hi.y = acc[tm][tn][3] * alpha;
            *(float2*)(C + (long long)row * ldc + col) = lo;
            *(float2*)(C + (long long)(row + 8) * ldc + col) = hi;
        }
    }
}

// ---------------------------------------------------------------------------
// fp32 -> hi/lo plane pack (vector of 4)
// ---------------------------------------------------------------------------
__global__ void __launch_bounds__(256) pack_plane_kernel(
    const float* __restrict__ in, u16* __restrict__ oh, u16* __restrict__ ol,
    long long n4)
{
    const long long i = (long long)blockIdx.x * 256 + threadIdx.x;
    if (i >= n4) return;
    const float4 v = ((const float4*)in)[i];
    ushort4 h4, l4;
    split_bf(v.x, h4.x, l4.x); split_bf(v.y, h4.y, l4.y);
    split_bf(v.z, h4.z, l4.z); split_bf(v.w, h4.w, l4.w);
    ((ushort4*)oh)[i] = h4;
    ((ushort4*)ol)[i] = l4;
}

// ---------------------------------------------------------------------------
// Transpose + split: out[c][r] = split(in[r][c])
// ---------------------------------------------------------------------------
__device__ __forceinline__ void transpose_tile(
    const float* __restrict__ in, u16* __restrict__ oh, u16* __restrict__ ol,
    int R, int C, int bx, int by, int x, int y, float* tile /*32x33*/)
{
    const int c0 = bx * 32;
    const int r0 = by * 32;
#pragma unroll
    for (int i = 0; i < 32; i += 8)
        tile[(y + i) * 33 + x] = in[(long long)(r0 + y + i) * C + c0 + x];
    __syncthreads();
#pragma unroll
    for (int i = 0; i < 32; i += 8) {
        u16 h, l;
        split_bf(tile[x * 33 + y + i], h, l);
        const long long o = (long long)(c0 + y + i) * R + r0 + x;
        oh[o] = h; ol[o] = l;
    }
}

__global__ void __launch_bounds__(256) transpose_plane_kernel(
    const float* __restrict__ in, u16* __restrict__ oh, u16* __restrict__ ol,
    int R, int C)
{
    __shared__ float tile[32 * 33];
    transpose_tile(in, oh, ol, R, C, blockIdx.x, blockIdx.y,
                   threadIdx.x, threadIdx.y, tile);
}

// all 4 weight transposes in ONE launch (flattened grid)
__global__ void __launch_bounds__(256) transpose_weights_kernel(
    const float* __restrict__ Wq, const float* __restrict__ Wk,
    const float* __restrict__ Wv, const float* __restrict__ Wo,
    u16* __restrict__ qh, u16* __restrict__ ql,
    u16* __restrict__ kh, u16* __restrict__ kl,
    u16* __restrict__ vh, u16* __restrict__ vl,
    u16* __restrict__ oh, u16* __restrict__ ol)
{
    __shared__ float tile[32 * 33];
    const int b = blockIdx.x;
    const float* in; u16 *ph, *pl; int R, C, local;
    if (b < 4096)      { in = Wq; ph = qh; pl = ql; R = HID; C = HID; local = b; }
    else if (b < 4608) { in = Wk; ph = kh; pl = kl; R = HID; C = HD;  local = b - 4096; }
    else if (b < 5120) { in = Wv; ph = vh; pl = vl; R = HID; C = HD;  local = b - 4608; }
    else               { in = Wo; ph = oh; pl = ol; R = HID; C = HID; local = b - 5120; }
    const int tc = C / 32;
    transpose_tile(in, ph, pl, R, C, local % tc, local / tc,
                   threadIdx.x, threadIdx.y, tile);
}

// ---------------------------------------------------------------------------
// RoPE: fp32 g_Q/g_K -> hi/lo planes
// ---------------------------------------------------------------------------
__global__ void rope_pack_kernel(const int* __restrict__ pos_ids)
{
    const int s = blockIdx.x;
    const int j = threadIdx.x;           // 0..127
    const float p = (float)pos_ids[s];
    const float inv = expf(-((float)j * (1.0f / 128.0f)) * logf(10000.0f));
    const float ang = p * inv;
    const float c  = cosf(ang);
    const float sn = sinf(ang);

#pragma unroll
    for (int h = 0; h < NH; h++) {
        const size_t o = (size_t)s * HID + h * HD;
        const float x1 = g_Q[o + j];
        const float x2 = g_Q[o + j + 128];
        u16 hh, ll;
        split_bf(x1 * c - x2 * sn, hh, ll);
        g_Qhi[o + j] = hh; g_Qlo[o + j] = ll;
        split_bf(x2 * c + x1 * sn, hh, ll);
        g_Qhi[o + j + 128] = hh; g_Qlo[o + j + 128] = ll;
    }
    const size_t o = (size_t)s * HD;
    const float x1 = g_K[o + j];
    const float x2 = g_K[o + j + 128];
    u16 hh, ll;
    split_bf(x1 * c - x2 * sn, hh, ll);
    g_Khi[o + j] = hh; g_Klo[o + j] = ll;
    split_bf(x2 * c + x1 * sn, hh, ll);
    g_Khi[o + j + 128] = hh; g_Klo[o + j + 128] = ll;
}

// ---------------------------------------------------------------------------
// Softmax: one block per q row, all 8 heads; mask row staged in SMEM once.
// ---------------------------------------------------------------------------
__global__ void __launch_bounds__(256) softmax_kernel(const float* __restrict__ mask)
{
    const int q = blockIdx.x;
    const int tid = threadIdx.x;
    __shared__ float msk[S_LEN];
    __shared__ float red[256];

    const float* __restrict__ mrow = mask + (size_t)q * S_LEN;
#pragma unroll
    for (int i = 0; i < 16; i++) msk[tid + i * 256] = mrow[tid + i * 256];
    __syncthreads();

    for (int h = 0; h < NH; h++) {
        const size_t ro = ((size_t)h * S_LEN + q) * S_LEN;
        const float* __restrict__ row = g_S + ro;

        float v[16];
        float m = -1e30f;
#pragma unroll
        for (int i = 0; i < 16; i++) {
            const int k = tid + i * 256;
            v[i] = row[k] + msk[k];
            m = fmaxf(m, v[i]);
        }
        red[tid] = m;
        __syncthreads();
        for (int st = 128; st > 0; st >>= 1) {
            if (tid < st) red[tid] = fmaxf(red[tid], red[tid + st]);
            __syncthreads();
        }
        m = red[0];
        __syncthreads();

        float sum = 0.0f;
#pragma unroll
        for (int i = 0; i < 16; i++) {
            v[i] = __expf(v[i] - m);
            sum += v[i];
        }
        red[tid] = sum;
        __syncthreads();
        for (int st = 128; st > 0; st >>= 1) {
            if (tid < st) red[tid] += red[tid + st];
            __syncthreads();
        }
        const float inv = 1.0f / red[0];
        __syncthreads();

#pragma unroll
        for (int i = 0; i < 16; i++) {
            const int k = tid + i * 256;
            u16 hh, ll;
            split_bf(v[i] * inv, hh, ll);
            g_Phi[ro + k] = hh;
            g_Plo[ro + k] = ll;
        }
    }
}

// ---------------------------------------------------------------------------
// Launch.  Order keeps launch #4 (ncu capture slot) = Q projection GEMM.
// ---------------------------------------------------------------------------
extern "C" void kernel_launch(void* const* d_in, const int* in_sizes, int n_in,
                              void* d_out, int out_size)
{
    const float* X    = (const float*)d_in[0];
    const float* mask = (const float*)d_in[1];
    const int*   pos  = (const int*)d_in[2];
    const float* Wq   = (const float*)d_in[3];
    const float* Wk   = (const float*)d_in[4];
    const float* Wv   = (const float*)d_in[5];
    const float* Wo   = (const float*)d_in[6];
    float* out = (float*)d_out;

    float *Q, *K, *V, *Sb, *A;
    u16 *Xhi,*Xlo,*Qhi,*Qlo,*Khi,*Klo,*VThi,*VTlo,*Phi,*Plo,*Ahi,*Alo;
    u16 *WqThi,*WqTlo,*WkThi,*WkTlo,*WvThi,*WvTlo,*WoThi,*WoTlo;
    cudaGetSymbolAddress((void**)&Q,   g_Q);
    cudaGetSymbolAddress((void**)&K,   g_K);
    cudaGetSymbolAddress((void**)&V,   g_V);
    cudaGetSymbolAddress((void**)&Sb,  g_S);
    cudaGetSymbolAddress((void**)&A,   g_A);
    cudaGetSymbolAddress((void**)&Xhi, g_Xhi);  cudaGetSymbolAddress((void**)&Xlo, g_Xlo);
    cudaGetSymbolAddress((void**)&Qhi, g_Qhi);  cudaGetSymbolAddress((void**)&Qlo, g_Qlo);
    cudaGetSymbolAddress((void**)&Khi, g_Khi);  cudaGetSymbolAddress((void**)&Klo, g_Klo);
    cudaGetSymbolAddress((void**)&VThi,g_VThi); cudaGetSymbolAddress((void**)&VTlo,g_VTlo);
    cudaGetSymbolAddress((void**)&Phi, g_Phi);  cudaGetSymbolAddress((void**)&Plo, g_Plo);
    cudaGetSymbolAddress((void**)&Ahi, g_Ahi);  cudaGetSymbolAddress((void**)&Alo, g_Alo);
    cudaGetSymbolAddress((void**)&WqThi,g_WqThi); cudaGetSymbolAddress((void**)&WqTlo,g_WqTlo);
    cudaGetSymbolAddress((void**)&WkThi,g_WkThi); cudaGetSymbolAddress((void**)&WkTlo,g_WkTlo);
    cudaGetSymbolAddress((void**)&WvThi,g_WvThi); cudaGetSymbolAddress((void**)&WvTlo,g_WvTlo);
    cudaGetSymbolAddress((void**)&WoThi,g_WoThi); cudaGetSymbolAddress((void**)&WoTlo,g_WoTlo);

    cudaFuncSetAttribute(bgemm, cudaFuncAttributeMaxDynamicSharedMemorySize, GEMM_SMEM);

    // 1: pack X
    pack_plane_kernel<<<(S_LEN * HID / 4 + 255) / 256, 256>>>(
        X, Xhi, Xlo, (long long)S_LEN * HID / 4);
    // 2: all weight transposes
    transpose_weights_kernel<<<9216, dim3(32, 8)>>>(
        Wq, Wk, Wv, Wo, WqThi, WqTlo, WkThi, WkTlo, WvThi, WvTlo, WoThi, WoTlo);
    // 3: K projection
    bgemm<<<dim3(HD / 128, S_LEN / 128, 1), 256, GEMM_SMEM>>>(
        Xhi, Xlo, WkThi, WkTlo, K, HID, HID, HID, HD, 0, 0, 0, 1.0f);
    // 4: Q projection  (ncu capture slot)
    bgemm<<<dim3(HID / 128, S_LEN / 128, 1), 256, GEMM_SMEM>>>(
        Xhi, Xlo, WqThi, WqTlo, Q, HID, HID, HID, HID, 0, 0, 0, 1.0f);
    // 5: V projection
    bgemm<<<dim3(HD / 128, S_LEN / 128, 1), 256, GEMM_SMEM>>>(
        Xhi, Xlo, WvThi, WvTlo, V, HID, HID, HID, HD, 0, 0, 0, 1.0f);
    // 6: RoPE -> packed planes
    rope_pack_kernel<<<S_LEN, 128>>>(pos);
    // 7: V^T planes
    transpose_plane_kernel<<<dim3(HD / 32, S_LEN / 32), dim3(32, 8)>>>(
        V, VThi, VTlo, S_LEN, HD);
    // 8: scores = (Q K^T)/16
    bgemm<<<dim3(S_LEN / 128, S_LEN / 128, NH), 256, GEMM_SMEM>>>(
        Qhi, Qlo, Khi, Klo, Sb, HD, HID, HD, S_LEN,
        (long long)HD, 0, (long long)S_LEN * S_LEN, 1.0f / 16.0f);
    // 9: softmax -> P planes
    softmax_kernel<<<S_LEN, 256>>>(mask);
    // 10: A = P @ V
    bgemm<<<dim3(HD / 128, S_LEN / 128, NH), 256, GEMM_SMEM>>>(
        Phi, Plo, VThi, VTlo, A, S_LEN, S_LEN, S_LEN, HID,
        (long long)S_LEN * S_LEN, 0, (long long)HD, 1.0f);
    // 11: pack A
    pack_plane_kernel<<<(S_LEN * HID / 4 + 255) / 256, 256>>>(
        A, Ahi, Alo, (long long)S_LEN * HID / 4);
    // 12: out = A @ Wo
    bgemm<<<dim3(HID / 128, S_LEN / 128, 1), 256, GEMM_SMEM>>>(
        Ahi, Alo, WoThi, WoTlo, out, HID, HID, HID, HID, 0, 0, 0, 1.0f);
}

// round 8
// speedup vs baseline: 1.9552x; 1.5694x over previous
#include <cuda_runtime.h>
#include <cuda_fp16.h>
#include <math.h>
#include <cstdint>

#define S_LEN 4096
#define HID   2048
#define NH    8
#define HD    256
#define NQKV  2560      // 2048 (Q) + 256 (K) + 256 (V)

typedef unsigned short u16;

// ------------------------- device scratch (no allocs allowed) ---------------
__device__ float g_QKV[(size_t)S_LEN * NQKV];        // 40 MB fp32 proj out
__device__ float g_S  [(size_t)NH * S_LEN * S_LEN];  // 512 MB fp32 scores

__device__ u16 g_Xh  [(size_t)S_LEN * HID];          // fp16 single planes (A-side)
__device__ u16 g_Qh  [(size_t)S_LEN * HID];
__device__ u16 g_P   [(size_t)NH * S_LEN * S_LEN];   // 268 MB fp16 P
__device__ u16 g_Ah  [(size_t)S_LEN * HID];
__device__ u16 g_Khi [(size_t)S_LEN * HD];           // fp16 hi/lo planes (B-side)
__device__ u16 g_Klo [(size_t)S_LEN * HD];
__device__ u16 g_VThi[(size_t)HD * S_LEN];
__device__ u16 g_VTlo[(size_t)HD * S_LEN];
__device__ u16 g_Whi [(size_t)NQKV * HID];           // concat Wq|Wk|Wv transposed, x64
__device__ u16 g_Wlo [(size_t)NQKV * HID];
__device__ u16 g_WoThi[(size_t)HID * HID];           // Wo transposed, x64
__device__ u16 g_WoTlo[(size_t)HID * HID];

// ------------------------- helpers ------------------------------------------
__device__ __forceinline__ void split_h(float x, u16& h, u16& l) {
    __half hh = __float2half_rn(x);
    __half ll = __float2half_rn(x - __half2float(hh));
    h = __half_as_ushort(hh);
    l = __half_as_ushort(ll);
}
__device__ __forceinline__ u16 to_h(float x) {
    return __half_as_ushort(__float2half_rn(x));
}
__device__ __forceinline__ uint32_t smem_u32(const void* p) {
    uint32_t a;
    asm("{ .reg .u64 t; cvta.to.shared.u64 t, %1; cvt.u32.u64 %0, t; }"
        : "=r"(a) : "l"(p));
    return a;
}
__device__ __forceinline__ void cpa16(uint32_t dst, const void* src) {
    asm volatile("cp.async.cg.shared.global [%0], [%1], 16;" :: "r"(dst), "l"(src));
}
__device__ __forceinline__ void cpa_commit() {
    asm volatile("cp.async.commit_group;");
}

#define LDSM4(r, a)                                                            \
    asm volatile("ldmatrix.sync.aligned.m8n8.x4.shared.b16 {%0,%1,%2,%3}, [%4];" \
        : "=r"((r)[0]), "=r"((r)[1]), "=r"((r)[2]), "=r"((r)[3]) : "r"(a))

#define MMA_F16(acc, a, b)                                                     \
    asm volatile(                                                              \
        "mma.sync.aligned.m16n8k16.row.col.f32.f16.f16.f32 "                   \
        "{%0,%1,%2,%3},{%4,%5,%6,%7},{%8,%9},{%0,%1,%2,%3};"                   \
        : "+f"((acc)[0]), "+f"((acc)[1]), "+f"((acc)[2]), "+f"((acc)[3])       \
        : "r"((a)[0]), "r"((a)[1]), "r"((a)[2]), "r"((a)[3]),                  \
          "r"((b)[0]), "r"((b)[1]))

// epilogue store overloads
__device__ __forceinline__ void store2(float* C, long long idx, float a, float b) {
    *(float2*)(C + idx) = make_float2(a, b);
}
__device__ __forceinline__ void store2(u16* C, long long idx, float a, float b) {
    *(__half2*)(C + idx) = __floats2half2_rn(a, b);
}

// ---------------------------------------------------------------------------
// fp16 one-sided-split GEMM (NT): C[m,n] = alpha * sum_k A[m,k]*B[n,k]
// A: single fp16 plane. B: fp16 hi + lo planes (2 MMA passes).
// CTA 128x128, K-chunk 32, 256 threads, 4 SMEM buffers / 3 in-flight groups,
// one __syncthreads per chunk, 2 CTAs/SM.
// SMEM rows: 32 u16 = 64 B, XOR swizzle (g' = g ^ ((row>>1)&3)).
// ---------------------------------------------------------------------------
#define PLANE_B  (128 * 64)          // 8192 B
#define STAGE_B  (3 * PLANE_B)       // 24576 B: A, Bhi, Blo
#define NSTAGE   4
#define GEMM_SMEM (NSTAGE * STAGE_B) // 98304 B

template <typename OT>
__global__ void __launch_bounds__(256, 2) bgemm(
    const u16* __restrict__ A,
    const u16* __restrict__ Bhi, const u16* __restrict__ Blo,
    OT* __restrict__ C,
    int K, int lda, int ldb, int ldc,
    long long sA, long long sB, long long sC, float alpha)
{
    extern __shared__ u16 smraw[];
    const uint32_t smb = smem_u32(smraw);

    const int tid  = threadIdx.x;
    const int wid  = tid >> 5;
    const int lane = tid & 31;
    const int g    = lane >> 2;
    const int tg   = lane & 3;
    const int wm   = (wid >> 2) * 64;
    const int wn   = (wid & 3) * 32;

    const int z  = blockIdx.z;
    const int m0 = blockIdx.y * 128;
    const int n0 = blockIdx.x * 128;
    const u16* gA  = A   + (long long)z * sA + (long long)m0 * lda;
    const u16* gBh = Bhi + (long long)z * sB + (long long)n0 * ldb;
    const u16* gBl = Blo + (long long)z * sB + (long long)n0 * ldb;
    C += (long long)z * sC;

    const int r_lo = tid >> 2;       // 0..63
    const int c16  = tid & 3;        // 16B granule in 64B row

    auto issue = [&](int c) {
        const uint32_t sbase = smb + (uint32_t)(c & (NSTAGE - 1)) * STAGE_B;
        const int k0 = c << 5;
#pragma unroll
        for (int t = 0; t < 6; t++) {
            const int p   = t >> 1;
            const int row = ((t & 1) << 6) + r_lo;
            const int gsw = c16 ^ ((row >> 1) & 3);
            const u16* src = (p == 0) ? gA : (p == 1) ? gBh : gBl;
            const int ld   = (p == 0) ? lda : ldb;
            cpa16(sbase + (uint32_t)(p * PLANE_B + row * 64 + (gsw << 4)),
                  src + (long long)row * ld + k0 + c16 * 8);
        }
        cpa_commit();
    };

    float acc[4][4][4];
#pragma unroll
    for (int i = 0; i < 4; i++)
#pragma unroll
        for (int j = 0; j < 4; j++)
#pragma unroll
            for (int r = 0; r < 4; r++) acc[i][j][r] = 0.0f;

    // per-lane ldmatrix offsets
    const int l8 = lane & 7;
    const int lt = lane >> 3;
    const int rA = ((lt & 1) << 3) + l8;
    const int gA4 = lt >> 1;
    const int rB = ((lt >> 1) << 3) + l8;
    const int gB4 = lt & 1;

    uint32_t offA[4][2], offB[2][2];
#pragma unroll
    for (int tm = 0; tm < 4; tm++) {
        const int R = wm + tm * 16 + rA;
        const int sw = (R >> 1) & 3;
#pragma unroll
        for (int ks = 0; ks < 2; ks++)
            offA[tm][ks] = (uint32_t)(R * 64 + (((ks * 2 + gA4) ^ sw) << 4));
    }
#pragma unroll
    for (int j = 0; j < 2; j++) {
        const int R = wn + j * 16 + rB;
        const int sw = (R >> 1) & 3;
#pragma unroll
        for (int ks = 0; ks < 2; ks++)
            offB[j][ks] = (uint32_t)(R * 64 + (((ks * 2 + gB4) ^ sw) << 4));
    }

    const int nc = K >> 5;
    issue(0);
    if (nc > 1) issue(1);
    if (nc > 2) issue(2);

    for (int c = 0; c < nc; c++) {
        if (c <= nc - 3)      asm volatile("cp.async.wait_group 2;");
        else if (c == nc - 2) asm volatile("cp.async.wait_group 1;");
        else                  asm volatile("cp.async.wait_group 0;");
        __syncthreads();
        if (c + 3 < nc) issue(c + 3);

        const uint32_t st  = smb + (uint32_t)(c & (NSTAGE - 1)) * STAGE_B;
        const uint32_t aPl = st;
        const uint32_t bHi = st + PLANE_B;
        const uint32_t bLo = st + 2 * PLANE_B;

#pragma unroll
        for (int ks = 0; ks < 2; ks++) {
            uint32_t bhi[4][2], blo[4][2];
#pragma unroll
            for (int j = 0; j < 2; j++) {
                uint32_t r[4];
                LDSM4(r, bHi + offB[j][ks]);
                bhi[2 * j][0] = r[0]; bhi[2 * j][1] = r[1];
                bhi[2 * j + 1][0] = r[2]; bhi[2 * j + 1][1] = r[3];
                LDSM4(r, bLo + offB[j][ks]);
                blo[2 * j][0] = r[0]; blo[2 * j][1] = r[1];
                blo[2 * j + 1][0] = r[2]; blo[2 * j + 1][1] = r[3];
            }
#pragma unroll
            for (int tm = 0; tm < 4; tm++) {
                uint32_t a[4];
                LDSM4(a, aPl + offA[tm][ks]);
#pragma unroll
                for (int tn = 0; tn < 4; tn++) MMA_F16(acc[tm][tn], a, bhi[tn]);
#pragma unroll
                for (int tn = 0; tn < 4; tn++) MMA_F16(acc[tm][tn], a, blo[tn]);
            }
        }
    }

    // epilogue
#pragma unroll
    for (int tm = 0; tm < 4; tm++) {
        const int row = m0 + wm + tm * 16 + g;
#pragma unroll
        for (int tn = 0; tn < 4; tn++) {
            const int col = n0 + wn + tn * 8 + 2 * tg;
            store2(C, (long long)row * ldc + col,
                   acc[tm][tn][0] * alpha, acc[tm][tn][1] * alpha);
            store2(C, (long long)(row + 8) * ldc + col,
                   acc[tm][tn][2] * alpha, acc[tm][tn][3] * alpha);
        }
    }
}

// ---------------------------------------------------------------------------
// fp32 -> fp16 single-plane pack
// ---------------------------------------------------------------------------
__global__ void __launch_bounds__(256) pack_half_kernel(
    const float* __restrict__ in, u16* __restrict__ out, long long n4)
{
    const long long i = (long long)blockIdx.x * 256 + threadIdx.x;
    if (i >= n4) return;
    const float4 v = ((const float4*)in)[i];
    ushort4 o;
    o.x = to_h(v.x); o.y = to_h(v.y); o.z = to_h(v.z); o.w = to_h(v.w);
    ((ushort4*)out)[i] = o;
}

// ---------------------------------------------------------------------------
// Weight transpose + x64 scale + fp16 split.
// Blocks 0..5119: QKV concat -> g_Whi/lo [2560, 2048]
// Blocks 5120..9215: Wo -> g_WoThi/lo [2048, 2048]
// ---------------------------------------------------------------------------
__global__ void __launch_bounds__(256) transpose_weights_kernel(
    const float* __restrict__ Wq, const float* __restrict__ Wk,
    const float* __restrict__ Wv, const float* __restrict__ Wo)
{
    __shared__ float tile[32][33];
    const int b = blockIdx.x;
    const int x = threadIdx.x;
    const int y = threadIdx.y;

    const float* src; int scol, sC, n0, k0;
    u16 *oh, *ol;
    if (b < 5120) {
        const int bx = b % 80, by = b / 80;
        n0 = bx * 32; k0 = by * 32;
        if (n0 < 2048)      { src = Wq; scol = n0;        sC = 2048; }
        else if (n0 < 2304) { src = Wk; scol = n0 - 2048; sC = 256; }
        else                { src = Wv; scol = n0 - 2304; sC = 256; }
        oh = g_Whi; ol = g_Wlo;
    } else {
        const int bb = b - 5120;
        const int bx = bb % 64, by = bb / 64;
        n0 = bx * 32; k0 = by * 32;
        src = Wo; scol = n0; sC = 2048;
        oh = g_WoThi; ol = g_WoTlo;
    }
#pragma unroll
    for (int i = 0; i < 32; i += 8)
        tile[y + i][x] = src[(long long)(k0 + y + i) * sC + scol + x];
    __syncthreads();
#pragma unroll
    for (int i = 0; i < 32; i += 8) {
        u16 h, l;
        split_h(tile[x][y + i] * 64.0f, h, l);
        const long long o = (long long)(n0 + y + i) * HID + k0 + x;
        oh[o] = h; ol[o] = l;
    }
}

// ---------------------------------------------------------------------------
// RoPE: g_QKV -> Qh single fp16 plane, K hi/lo planes
// ---------------------------------------------------------------------------
__global__ void rope_kernel(const int* __restrict__ pos_ids)
{
    const int s = blockIdx.x;
    const int j = threadIdx.x;           // 0..127
    const float p = (float)pos_ids[s];
    const float inv = expf(-((float)j * (1.0f / 128.0f)) * logf(10000.0f));
    const float ang = p * inv;
    const float c  = cosf(ang);
    const float sn = sinf(ang);

    const float* row = g_QKV + (size_t)s * NQKV;
#pragma unroll
    for (int h = 0; h < NH; h++) {
        const float x1 = row[h * HD + j];
        const float x2 = row[h * HD + j + 128];
        const size_t o = (size_t)s * HID + h * HD;
        g_Qh[o + j]       = to_h(x1 * c - x2 * sn);
        g_Qh[o + j + 128] = to_h(x2 * c + x1 * sn);
    }
    {
        const float x1 = row[2048 + j];
        const float x2 = row[2048 + j + 128];
        const size_t o = (size_t)s * HD;
        u16 hh, ll;
        split_h(x1 * c - x2 * sn, hh, ll);
        g_Khi[o + j] = hh; g_Klo[o + j] = ll;
        split_h(x2 * c + x1 * sn, hh, ll);
        g_Khi[o + j + 128] = hh; g_Klo[o + j + 128] = ll;
    }
}

// ---------------------------------------------------------------------------
// V transpose: g_QKV cols [2304,2560) -> VT hi/lo [256, 4096]
// grid (256/32, 4096/32) = (8, 128)
// ---------------------------------------------------------------------------
__global__ void __launch_bounds__(256) transpose_v_kernel()
{
    __shared__ float tile[32][33];
    const int c0 = blockIdx.x * 32;    // d
    const int r0 = blockIdx.y * 32;    // s
    const int x = threadIdx.x;
    const int y = threadIdx.y;
#pragma unroll
    for (int i = 0; i < 32; i += 8)
        tile[y + i][x] = g_QKV[(size_t)(r0 + y + i) * NQKV + 2304 + c0 + x];
    __syncthreads();
#pragma unroll
    for (int i = 0; i < 32; i += 8) {
        u16 h, l;
        split_h(tile[x][y + i], h, l);
        const size_t o = (size_t)(c0 + y + i) * S_LEN + r0 + x;
        g_VThi[o] = h; g_VTlo[o] = l;
    }
}

// ---------------------------------------------------------------------------
// Softmax: one block per q row, all 8 heads; mask staged once; writes fp16 P.
// ---------------------------------------------------------------------------
__global__ void __launch_bounds__(256) softmax_kernel(const float* __restrict__ mask)
{
    const int q = blockIdx.x;
    const int tid = threadIdx.x;
    __shared__ float msk[S_LEN];
    __shared__ float red[256];

    const float* __restrict__ mrow = mask + (size_t)q * S_LEN;
#pragma unroll
    for (int i = 0; i < 16; i++) msk[tid + i * 256] = mrow[tid + i * 256];
    __syncthreads();

    for (int h = 0; h < NH; h++) {
        const size_t ro = ((size_t)h * S_LEN + q) * S_LEN;
        const float* __restrict__ row = g_S + ro;

        float v[16];
        float m = -1e30f;
#pragma unroll
        for (int i = 0; i < 16; i++) {
            const int k = tid + i * 256;
            v[i] = row[k] + msk[k];
            m = fmaxf(m, v[i]);
        }
        red[tid] = m;
        __syncthreads();
        for (int st = 128; st > 0; st >>= 1) {
            if (tid < st) red[tid] = fmaxf(red[tid], red[tid + st]);
            __syncthreads();
        }
        m = red[0];
        __syncthreads();

        float sum = 0.0f;
#pragma unroll
        for (int i = 0; i < 16; i++) {
            v[i] = __expf(v[i] - m);
            sum += v[i];
        }
        red[tid] = sum;
        __syncthreads();
        for (int st = 128; st > 0; st >>= 1) {
            if (tid < st) red[tid] += red[tid + st];
            __syncthreads();
        }
        const float inv = 1.0f / red[0];
        __syncthreads();

#pragma unroll
        for (int i = 0; i < 16; i++)
            g_P[ro + tid + i * 256] = to_h(v[i] * inv);
    }
}

// ---------------------------------------------------------------------------
// Launch.  #4 (ncu capture slot) = merged QKV projection GEMM.
// ---------------------------------------------------------------------------
extern "C" void kernel_launch(void* const* d_in, const int* in_sizes, int n_in,
                              void* d_out, int out_size)
{
    const float* X    = (const float*)d_in[0];
    const float* mask = (const float*)d_in[1];
    const int*   pos  = (const int*)d_in[2];
    const float* Wq   = (const float*)d_in[3];
    const float* Wk   = (const float*)d_in[4];
    const float* Wv   = (const float*)d_in[5];
    const float* Wo   = (const float*)d_in[6];
    float* out = (float*)d_out;

    float *QKV, *Sb;
    u16 *Xh, *Qh, *Khi, *Klo, *VThi, *VTlo, *P, *Ah, *Whi, *Wlo, *WoThi, *WoTlo;
    cudaGetSymbolAddress((void**)&QKV,  g_QKV);
    cudaGetSymbolAddress((void**)&Sb,   g_S);
    cudaGetSymbolAddress((void**)&Xh,   g_Xh);
    cudaGetSymbolAddress((void**)&Qh,   g_Qh);
    cudaGetSymbolAddress((void**)&Khi,  g_Khi);
    cudaGetSymbolAddress((void**)&Klo,  g_Klo);
    cudaGetSymbolAddress((void**)&VThi, g_VThi);
    cudaGetSymbolAddress((void**)&VTlo, g_VTlo);
    cudaGetSymbolAddress((void**)&P,    g_P);
    cudaGetSymbolAddress((void**)&Ah,   g_Ah);
    cudaGetSymbolAddress((void**)&Whi,  g_Whi);
    cudaGetSymbolAddress((void**)&Wlo,  g_Wlo);
    cudaGetSymbolAddress((void**)&WoThi, g_WoThi);
    cudaGetSymbolAddress((void**)&WoTlo, g_WoTlo);

    cudaFuncSetAttribute(bgemm<float>, cudaFuncAttributeMaxDynamicSharedMemorySize, GEMM_SMEM);
    cudaFuncSetAttribute(bgemm<u16>,   cudaFuncAttributeMaxDynamicSharedMemorySize, GEMM_SMEM);

    const long long n4 = (long long)S_LEN * HID / 4;   // 2M float4s
    // 1,2: pack X (two halves so launch #4 lands on the QKV GEMM)
    pack_half_kernel<<<(int)(n4 / 2 / 256), 256>>>(X, Xh, n4 / 2);
    pack_half_kernel<<<(int)(n4 / 2 / 256), 256>>>(
        X + n4 / 2 * 4, Xh + n4 / 2 * 4, n4 / 2);
    // 3: weight transposes (+x64 scale, fp16 split)
    transpose_weights_kernel<<<9216, dim3(32, 8)>>>(Wq, Wk, Wv, Wo);
    // 4: merged QKV projection: [4096,2560] = X @ Wqkv   (alpha descales x64)
    bgemm<float><<<dim3(NQKV / 128, S_LEN / 128, 1), 256, GEMM_SMEM>>>(
        Xh, Whi, Wlo, QKV, HID, HID, HID, NQKV, 0, 0, 0, 1.0f / 64.0f);
    // 5: RoPE -> Qh, Khi/Klo
    rope_kernel<<<S_LEN, 128>>>(pos);
    // 6: V^T hi/lo
    transpose_v_kernel<<<dim3(HD / 32, S_LEN / 32), dim3(32, 8)>>>();
    // 7: scores = (Q K^T)/16
    bgemm<float><<<dim3(S_LEN / 128, S_LEN / 128, NH), 256, GEMM_SMEM>>>(
        Qh, Khi, Klo, Sb, HD, HID, HD, S_LEN,
        256LL, 0, (long long)S_LEN * S_LEN, 1.0f / 16.0f);
    // 8: softmax -> fp16 P
    softmax_kernel<<<S_LEN, 256>>>(mask);
    // 9: A' = P @ V  (fp16 output, written directly into Ah)
    bgemm<u16><<<dim3(HD / 128, S_LEN / 128, NH), 256, GEMM_SMEM>>>(
        P, VThi, VTlo, Ah, S_LEN, S_LEN, S_LEN, HID,
        (long long)S_LEN * S_LEN, 0, 256LL, 1.0f);
    // 10: out = A' @ Wo   (alpha descales x64)
    bgemm<float><<<dim3(HID / 128, S_LEN / 128, 1), 256, GEMM_SMEM>>>(
        Ah, WoThi, WoTlo, out, HID, HID, HID, HID, 0, 0, 0, 1.0f / 64.0f);
}